// round 9
// baseline (speedup 1.0000x reference)
#include <cuda_runtime.h>

// Problem constants (shapes fixed by the dataset)
#define MAXN 100000
#define MAXE 1600000
#define FEAT 64
#define DN 128            // nodes per dense block
#define AP 132            // act smem stride (multiple of 4 -> 16B-aligned rows)
#define SCAN_CHUNK 2048
#define MAXBLK 64

typedef unsigned long long ull;

// Scratch (__device__ globals; allocation-free rule). Zero-init at load;
// cleanup_kernel restores call-entry invariants every call.
__device__ float g_h1[MAXN * FEAT];
__device__ float g_agg[MAXN * FEAT];
__device__ int   g_cnt[MAXN];
__device__ int   g_off[MAXN];
__device__ int   g_cur[MAXN];
__device__ int   g_csr_src[MAXE];
__device__ int   g_bsum[MAXBLK];
__device__ int   g_bar;
// duplicated-transposed weights: [layer][phase][k][128] (f32x2 pairs per d)
__device__ float g_wdup[2 * 3 * 64 * 128];

// ---- packed f32x2 helpers (Blackwell PTX) ----------------------------------
__device__ __forceinline__ void fma2(ull& acc, ull av, ull wv)
{
    asm("fma.rn.f32x2 %0, %1, %2, %0;" : "+l"(acc) : "l"(av), "l"(wv));
}
__device__ __forceinline__ void unpk(float& lo, float& hi, ull v)
{
    asm("mov.b64 {%0, %1}, %2;" : "=f"(lo), "=f"(hi) : "l"(v));
}
__device__ __forceinline__ ull pk2(float lo, float hi)
{
    ull r; asm("mov.b64 %0, {%1, %2};" : "=l"(r) : "f"(lo), "f"(hi)); return r;
}

// ---------------------------------------------------------------------------
// Full-grid edge histogram + one-time weight preprocessing in extra blocks.
// wdup blocks write each weight as a duplicated f32x2 pair, transposed [k][2d].
// ---------------------------------------------------------------------------
__global__ void hist_wdup_kernel(const int* __restrict__ dst, int E, int eblocks,
                                 const float* __restrict__ wl0,
                                 const float* __restrict__ wr0,
                                 const float* __restrict__ ws0,
                                 const float* __restrict__ wl1,
                                 const float* __restrict__ wr1,
                                 const float* __restrict__ ws1)
{
    if ((int)blockIdx.x < eblocks) {
        int e = blockIdx.x * blockDim.x + threadIdx.x;
        if (e < E) atomicAdd(&g_cnt[dst[e]], 1);
    } else {
        int idx = (blockIdx.x - eblocks) * blockDim.x + threadIdx.x; // [0, 24576)
        int l   = idx / 12288;
        int rem = idx % 12288;
        int p   = rem / 4096;
        int r2  = rem % 4096;
        int kk  = r2 >> 6;       // k
        int dd  = r2 & 63;       // d (lanes vary d -> coalesced STG.64)
        const float* w = (l == 0) ? ((p == 0) ? wl0 : (p == 1) ? wr0 : ws0)
                                  : ((p == 0) ? wl1 : (p == 1) ? wr1 : ws1);
        float v = w[dd * 64 + kk];
        float2 pv; pv.x = v; pv.y = v;
        *(float2*)&g_wdup[(((l * 3 + p) * 64 + kk) << 7) + 2 * dd] = pv;
    }
}

// Software grid barrier (49 blocks co-resident on 148 SMs).
__device__ __forceinline__ void grid_bar(int target)
{
    __syncthreads();
    if (threadIdx.x == 0) {
        __threadfence();
        atomicAdd(&g_bar, 1);
        while (atomicAdd(&g_bar, 0) < target) { }
    }
    __syncthreads();
}

// ---------------------------------------------------------------------------
// Scan + fill (49 blocks): local exclusive scan -> bar -> global offsets ->
// bar -> bucket edges by dst (unroll 8 -> 8 atomic chains in flight).
// ---------------------------------------------------------------------------
__global__ void scanfill_kernel(const int* __restrict__ src,
                                const int* __restrict__ dst,
                                int N, int E, int nb)
{
    __shared__ int s_sum[256];
    int t = threadIdx.x;

    int base = blockIdx.x * SCAN_CHUNK + t * 8;
    int v[8], tot = 0;
#pragma unroll
    for (int j = 0; j < 8; j++) {
        int idx = base + j;
        v[j] = (idx < N) ? g_cnt[idx] : 0;
        tot += v[j];
    }
    s_sum[t] = tot;
    __syncthreads();
    for (int off = 1; off < 256; off <<= 1) {
        int xv = (t >= off) ? s_sum[t - off] : 0;
        __syncthreads();
        s_sum[t] += xv;
        __syncthreads();
    }
    if (t == 255) g_bsum[blockIdx.x] = s_sum[255];
    int run = s_sum[t] - tot;

    grid_bar(nb);

    int bpre = 0;
    for (int b = 0; b < (int)blockIdx.x; b++) bpre += g_bsum[b];
    run += bpre;
#pragma unroll
    for (int j = 0; j < 8; j++) {
        int idx = base + j;
        if (idx < N) { g_off[idx] = run; g_cur[idx] = run; }
        run += v[j];
    }

    grid_bar(2 * nb);

    // fill, 8 independent atomic chains per thread
    int tg = blockIdx.x * blockDim.x + t;
    int T  = gridDim.x * blockDim.x;
    for (int eb = tg * 8; eb < E; eb += T * 8) {
#pragma unroll
        for (int j = 0; j < 8; j++) {
            int e = eb + j;
            if (e < E) {
                int p = atomicAdd(&g_cur[dst[e]], 1);
                g_csr_src[p] = src[e];
            }
        }
    }
}

// ---------------------------------------------------------------------------
// Aggregate: one warp per node; lane covers feats (2l, 2l+1) as float2.
// At ~95% of the L2 data roofline already — keep.
// ---------------------------------------------------------------------------
__global__ void agg_kernel(const float* __restrict__ x, int N, int hFromH1)
{
    int node = (int)((blockIdx.x * blockDim.x + threadIdx.x) >> 5);
    int lane = threadIdx.x & 31;
    if (node >= N) return;
    const float2* h2 = (const float2*)(hFromH1 ? g_h1 : x);

    int start = g_off[node];
    int deg   = g_cnt[node];

    float ax = 0.f, ay = 0.f;
    int i = 0;
    for (; i + 8 <= deg; i += 8) {
        int s[8];
#pragma unroll
        for (int j = 0; j < 8; j++) s[j] = g_csr_src[start + i + j];
        float2 v[8];
#pragma unroll
        for (int j = 0; j < 8; j++) v[j] = h2[s[j] * 32 + lane];
        float sx = ((v[0].x + v[1].x) + (v[2].x + v[3].x))
                 + ((v[4].x + v[5].x) + (v[6].x + v[7].x));
        float sy = ((v[0].y + v[1].y) + (v[2].y + v[3].y))
                 + ((v[4].y + v[5].y) + (v[6].y + v[7].y));
        ax += sx; ay += sy;
    }
    for (; i < deg; i++) {
        int s = g_csr_src[start + i];
        float2 v = h2[s * 32 + lane];
        ax += v.x; ay += v.y;
    }
    float inv = 1.f / fmaxf((float)deg, 1.f);
    float2 r; r.x = ax * inv; r.y = ay * inv;
    ((float2*)g_agg)[node * 32 + lane] = r;
}

// ---------------------------------------------------------------------------
// Dense phase, fused per node n:
//   o = PReLU( agg[n]@wl^T + bl + h[n]@wr^T ) + x0[n]@ws^T + bs
// 256 threads tile 64 feats x 128 nodes; thread tile 4d x 8n. Weights come
// pre-duplicated/transposed from g_wdup -> staging is a straight LDG.128 ->
// STS.128 copy; per k: 2 LDS.128 (w pairs) + 2 LDS.128 (act broadcasts) +
// 16 fma.rn.f32x2. One packed acc set: phases 0,1 accumulate, bias+PReLU in
// registers, phase 2 on top. Layer 0 reuses the x act-tile for phase 2.
// ---------------------------------------------------------------------------
__global__ void __launch_bounds__(256, 3) dense_kernel(
    const float* __restrict__ x,
    const float* __restrict__ b_l, const float* __restrict__ b_skip,
    const float* __restrict__ a,
    float* __restrict__ out, int N, int layer)
{
    extern __shared__ __align__(16) float sm[];
    float* s_w   = sm;             // [64][128] packed f32x2 pairs
    float* s_act = sm + 64 * 128;  // [64][AP]

    int tid  = threadIdx.x;
    int base = blockIdx.x * DN;
    int d0   = (tid & 15) * 4;     // 4 output features
    int n0   = (tid >> 4) * 8;     // 8 nodes (4 f32x2 pairs)

    const float* h = layer ? g_h1 : x;
    const float* wbase = g_wdup + layer * 3 * 64 * 128;

    float bl[4], bs[4], apar[4];
#pragma unroll
    for (int dd = 0; dd < 4; dd++) {
        bl[dd]   = b_l[d0 + dd];
        bs[dd]   = b_skip[d0 + dd];
        apar[dd] = a[d0 + dd];
    }

    ull acc[4][4];
#pragma unroll
    for (int dd = 0; dd < 4; dd++)
#pragma unroll
        for (int p = 0; p < 4; p++) acc[dd][p] = 0ULL;

#pragma unroll
    for (int phase = 0; phase < 3; phase++) {
        bool reuseAct = (phase == 2) && (layer == 0);   // x already staged

        __syncthreads();
        // weights: straight conflict-free copy (8 x LDG.128 -> STS.128)
        {
            const float* wsrc = wbase + phase * 8192;
            for (int i = tid; i < 2048; i += 256)
                *(float4*)&s_w[i * 4] = *(const float4*)&wsrc[i * 4];
        }
        if (!reuseAct) {
            const float* am = (phase == 0) ? g_agg : (phase == 1) ? h : x;
            for (int i = tid; i < 2048; i += 256) {
                int n = i & 127, kq = i >> 7;       // lanes vary n -> STS conflict-free
                int gn = base + n;
                float4 v = make_float4(0.f, 0.f, 0.f, 0.f);
                if (gn < N) v = *(const float4*)&am[gn * FEAT + kq * 4];
                int k0 = kq * 4;
                s_act[(k0 + 0) * AP + n] = v.x;
                s_act[(k0 + 1) * AP + n] = v.y;
                s_act[(k0 + 2) * AP + n] = v.z;
                s_act[(k0 + 3) * AP + n] = v.w;
            }
        }
        __syncthreads();

#pragma unroll 4
        for (int k = 0; k < 64; k++) {
            longlong2 w01 = *(const longlong2*)&s_w[(k << 7) + 2 * d0];
            longlong2 w23 = *(const longlong2*)&s_w[(k << 7) + 2 * d0 + 4];
            longlong2 a01 = *(const longlong2*)&s_act[k * AP + n0];
            longlong2 a23 = *(const longlong2*)&s_act[k * AP + n0 + 4];
            ull wd[4] = { (ull)w01.x, (ull)w01.y, (ull)w23.x, (ull)w23.y };
            ull av[4] = { (ull)a01.x, (ull)a01.y, (ull)a23.x, (ull)a23.y };
#pragma unroll
            for (int dd = 0; dd < 4; dd++)
#pragma unroll
                for (int p = 0; p < 4; p++)
                    fma2(acc[dd][p], av[p], wd[dd]);
        }

        if (phase == 1) {
            // mid-epilogue in registers: acc = PReLU(acc + bl)
#pragma unroll
            for (int dd = 0; dd < 4; dd++)
#pragma unroll
                for (int p = 0; p < 4; p++) {
                    float lo, hi;
                    unpk(lo, hi, acc[dd][p]);
                    lo += bl[dd]; hi += bl[dd];
                    lo = (lo >= 0.f) ? lo : apar[dd] * lo;
                    hi = (hi >= 0.f) ? hi : apar[dd] * hi;
                    acc[dd][p] = pk2(lo, hi);
                }
        }
    }

    float* dstp = layer ? out : g_h1;
    float f[4][8];
#pragma unroll
    for (int dd = 0; dd < 4; dd++)
#pragma unroll
        for (int p = 0; p < 4; p++)
            unpk(f[dd][2 * p], f[dd][2 * p + 1], acc[dd][p]);
#pragma unroll
    for (int j = 0; j < 8; j++) {
        int gn = base + n0 + j;
        if (gn < N) {
            float4 v;
            v.x = f[0][j] + bs[0];
            v.y = f[1][j] + bs[1];
            v.z = f[2][j] + bs[2];
            v.w = f[3][j] + bs[3];
            *(float4*)&dstp[gn * FEAT + d0] = v;
        }
    }
}

// ---------------------------------------------------------------------------
// Cleanup: restore call-entry invariants (g_cnt=0, g_bar=0).
// ---------------------------------------------------------------------------
__global__ void cleanup_kernel(int N)
{
    int i = blockIdx.x * blockDim.x + threadIdx.x;
    if (i < N) g_cnt[i] = 0;
    if (i == 0) g_bar = 0;
}

// ---------------------------------------------------------------------------
// Launch sequence. Index 3 (ncu profiled slot) = layer-0 dense_kernel.
// ---------------------------------------------------------------------------
extern "C" void kernel_launch(void* const* d_in, const int* in_sizes, int n_in,
                              void* d_out, int out_size)
{
    const float* x  = (const float*)d_in[0];
    const int*   ei = (const int*)d_in[1];   // int32 (JAX x64 disabled)
    int N = in_sizes[0] / FEAT;
    int E = in_sizes[1] / 2;
    const int* src = ei;
    const int* dst = ei + E;

    const float* w_l0    = (const float*)d_in[2];
    const float* b_l0    = (const float*)d_in[3];
    const float* w_r0    = (const float*)d_in[4];
    const float* w_skip0 = (const float*)d_in[5];
    const float* b_skip0 = (const float*)d_in[6];
    const float* a0      = (const float*)d_in[7];
    const float* w_l1    = (const float*)d_in[8];
    const float* b_l1    = (const float*)d_in[9];
    const float* w_r1    = (const float*)d_in[10];
    const float* w_skip1 = (const float*)d_in[11];
    const float* b_skip1 = (const float*)d_in[12];
    const float* a1      = (const float*)d_in[13];
    float* out = (float*)d_out;

    size_t dsmem = (size_t)(64 * 128 + 64 * AP) * sizeof(float); // 66,560 B
    cudaFuncSetAttribute(dense_kernel, cudaFuncAttributeMaxDynamicSharedMemorySize,
                         (int)dsmem);

    int eblocks = (E + 255) / 256;
    int wblocks = (2 * 3 * 64 * 64) / 256;             // 96
    int nb      = (N + SCAN_CHUNK - 1) / SCAN_CHUNK;   // 49
    int ablocks = (N * 32 + 255) / 256;
    int dblocks = (N + DN - 1) / DN;
    int nblocks = (N + 255) / 256;

    hist_wdup_kernel<<<eblocks + wblocks, 256>>>(dst, E, eblocks,     // 0
                                                 w_l0, w_r0, w_skip0,
                                                 w_l1, w_r1, w_skip1);
    scanfill_kernel<<<nb, 256>>>(src, dst, N, E, nb);                 // 1

    agg_kernel<<<ablocks, 256>>>(x, N, 0);                            // 2
    dense_kernel<<<dblocks, 256, dsmem>>>(x, b_l0, b_skip0, a0,       // 3 <- profiled
                                          out, N, 0);

    agg_kernel<<<ablocks, 256>>>(x, N, 1);                            // 4
    dense_kernel<<<dblocks, 256, dsmem>>>(x, b_l1, b_skip1, a1,       // 5
                                          out, N, 1);

    cleanup_kernel<<<nblocks, 256>>>(N);                              // 6
}

// round 10
// speedup vs baseline: 1.3260x; 1.3260x over previous
#include <cuda_runtime.h>

// Problem constants (shapes fixed by the dataset)
#define MAXN 100000
#define MAXE 1600000
#define FEAT 64
#define DN 128            // nodes per dense block
#define AP 132            // act smem stride (16B-aligned rows)
#define WP 68             // weight smem stride (16B-aligned rows)
#define SCAN_CHUNK 2048
#define MAXBLK 64

typedef unsigned long long ull;

// Scratch (__device__ globals; allocation-free rule). Zero-init at load;
// cleanup_kernel restores call-entry invariants every call.
__device__ float g_h1[MAXN * FEAT];
__device__ float g_agg[MAXN * FEAT];
__device__ int   g_cnt[MAXN];
__device__ int   g_off[MAXN];
__device__ int   g_cur[MAXN];
__device__ int   g_csr_src[MAXE];
__device__ int   g_bsum[MAXBLK];
__device__ int   g_bar;

// ---- packed f32x2 helpers (Blackwell PTX) ----------------------------------
__device__ __forceinline__ void fma2(ull& acc, ull av, ull wv)
{
    asm("fma.rn.f32x2 %0, %1, %2, %0;" : "+l"(acc) : "l"(av), "l"(wv));
}
__device__ __forceinline__ ull dup2(float w)
{
    ull r; asm("mov.b64 %0, {%1, %1};" : "=l"(r) : "f"(w)); return r;
}
__device__ __forceinline__ void unpk(float& lo, float& hi, ull v)
{
    asm("mov.b64 {%0, %1}, %2;" : "=f"(lo), "=f"(hi) : "l"(v));
}
__device__ __forceinline__ ull pk2(float lo, float hi)
{
    ull r; asm("mov.b64 %0, {%1, %2};" : "=l"(r) : "f"(lo), "f"(hi)); return r;
}

// ---------------------------------------------------------------------------
// Edge histogram: full grid, one edge per thread (max MLP for the REDs).
// ---------------------------------------------------------------------------
__global__ void hist_kernel(const int* __restrict__ dst, int E)
{
    int e = blockIdx.x * blockDim.x + threadIdx.x;
    if (e < E) atomicAdd(&g_cnt[dst[e]], 1);
}

// Software grid barrier (49 blocks co-resident on 148 SMs).
__device__ __forceinline__ void grid_bar(int target)
{
    __syncthreads();
    if (threadIdx.x == 0) {
        __threadfence();
        atomicAdd(&g_bar, 1);
        while (atomicAdd(&g_bar, 0) < target) { }
    }
    __syncthreads();
}

// ---------------------------------------------------------------------------
// Scan + fill (49 blocks): local exclusive scan -> bar -> global offsets ->
// bar -> bucket edges by dst (unroll 8 -> 8 atomic chains in flight).
// ---------------------------------------------------------------------------
__global__ void scanfill_kernel(const int* __restrict__ src,
                                const int* __restrict__ dst,
                                int N, int E, int nb)
{
    __shared__ int s_sum[256];
    int t = threadIdx.x;

    int base = blockIdx.x * SCAN_CHUNK + t * 8;
    int v[8], tot = 0;
#pragma unroll
    for (int j = 0; j < 8; j++) {
        int idx = base + j;
        v[j] = (idx < N) ? g_cnt[idx] : 0;
        tot += v[j];
    }
    s_sum[t] = tot;
    __syncthreads();
    for (int off = 1; off < 256; off <<= 1) {
        int xv = (t >= off) ? s_sum[t - off] : 0;
        __syncthreads();
        s_sum[t] += xv;
        __syncthreads();
    }
    if (t == 255) g_bsum[blockIdx.x] = s_sum[255];
    int run = s_sum[t] - tot;

    grid_bar(nb);

    int bpre = 0;
    for (int b = 0; b < (int)blockIdx.x; b++) bpre += g_bsum[b];
    run += bpre;
#pragma unroll
    for (int j = 0; j < 8; j++) {
        int idx = base + j;
        if (idx < N) { g_off[idx] = run; g_cur[idx] = run; }
        run += v[j];
    }

    grid_bar(2 * nb);

    // fill: 8 independent atomic chains per thread
    int tg = blockIdx.x * blockDim.x + t;
    int T  = gridDim.x * blockDim.x;
    for (int eb = tg * 8; eb < E; eb += T * 8) {
#pragma unroll
        for (int j = 0; j < 8; j++) {
            int e = eb + j;
            if (e < E) {
                int p = atomicAdd(&g_cur[dst[e]], 1);
                g_csr_src[p] = src[e];
            }
        }
    }
}

// ---------------------------------------------------------------------------
// Aggregate: one warp per node; lane covers feats (2l, 2l+1) as float2.
// Measured at ~95% of the L2 data roofline (36 us) — keep as-is.
// ---------------------------------------------------------------------------
__global__ void agg_kernel(const float* __restrict__ x, int N, int hFromH1)
{
    int node = (int)((blockIdx.x * blockDim.x + threadIdx.x) >> 5);
    int lane = threadIdx.x & 31;
    if (node >= N) return;
    const float2* h2 = (const float2*)(hFromH1 ? g_h1 : x);

    int start = g_off[node];
    int deg   = g_cnt[node];

    float ax = 0.f, ay = 0.f;
    int i = 0;
    for (; i + 8 <= deg; i += 8) {
        int s[8];
#pragma unroll
        for (int j = 0; j < 8; j++) s[j] = g_csr_src[start + i + j];
        float2 v[8];
#pragma unroll
        for (int j = 0; j < 8; j++) v[j] = h2[s[j] * 32 + lane];
        float sx = ((v[0].x + v[1].x) + (v[2].x + v[3].x))
                 + ((v[4].x + v[5].x) + (v[6].x + v[7].x));
        float sy = ((v[0].y + v[1].y) + (v[2].y + v[3].y))
                 + ((v[4].y + v[5].y) + (v[6].y + v[7].y));
        ax += sx; ay += sy;
    }
    for (; i < deg; i++) {
        int s = g_csr_src[start + i];
        float2 v = h2[s * 32 + lane];
        ax += v.x; ay += v.y;
    }
    float inv = 1.f / fmaxf((float)deg, 1.f);
    float2 r; r.x = ax * inv; r.y = ay * inv;
    ((float2*)g_agg)[node * 32 + lane] = r;
}

// ---------------------------------------------------------------------------
// Dense phase (R8 form — the proven-fastest variant), fused per node n:
//   o = PReLU( agg[n]@wl^T + bl + h[n]@wr^T ) + x0[n]@ws^T + bs
// 256 threads tile 64 feats x 128 nodes; thread tile 4d x 8n. Per k:
// 1 LDS.128 weights (256B/warp, 2 wf) + 4 dup movs (ALU) + 2 LDS.128 act
// broadcasts (2 wf) + 16 fma.rn.f32x2 -> fma-pipe-bound (8 cyc vs 4 wf).
// One packed acc set: phases 0,1 accumulate, bias+PReLU in registers,
// phase 2 (skip) on top. Layer 0 reuses the x act-tile for phase 2.
// ---------------------------------------------------------------------------
__global__ void __launch_bounds__(256, 3) dense_kernel(
    const float* __restrict__ x,
    const float* __restrict__ w_l, const float* __restrict__ b_l,
    const float* __restrict__ w_r, const float* __restrict__ w_skip,
    const float* __restrict__ b_skip, const float* __restrict__ a,
    float* __restrict__ out, int N, int hFromH1, int outToH1)
{
    extern __shared__ __align__(16) float sm[];
    float* s_w   = sm;            // [64][WP]
    float* s_act = sm + 64 * WP;  // [64][AP]

    int tid  = threadIdx.x;
    int base = blockIdx.x * DN;
    int d0   = (tid & 15) * 4;    // 4 consecutive output features (16B-aligned)
    int n0   = (tid >> 4) * 8;    // 8 nodes (4 f32x2 pairs)

    const float* h = hFromH1 ? g_h1 : x;
    const bool hIsX = (hFromH1 == 0);

    float bl[4], bs[4], apar[4];
#pragma unroll
    for (int dd = 0; dd < 4; dd++) {
        bl[dd]   = b_l[d0 + dd];
        bs[dd]   = b_skip[d0 + dd];
        apar[dd] = a[d0 + dd];
    }

    ull acc[4][4];                // [dd][pair]
#pragma unroll
    for (int dd = 0; dd < 4; dd++)
#pragma unroll
        for (int p = 0; p < 4; p++) acc[dd][p] = 0ULL;

#pragma unroll
    for (int phase = 0; phase < 3; phase++) {
        const float* wsrc = (phase == 0) ? w_l : (phase == 1) ? w_r : w_skip;
        bool reuseAct = (phase == 2) && hIsX;   // layer 0: x already staged

        __syncthreads();
        // stage weights transposed: w[dd][kk] -> s_w[kk*WP + dd]
        for (int i = tid; i < 64 * 64; i += 256) {
            int dd = i >> 6, kk = i & 63;
            s_w[kk * WP + dd] = wsrc[i];
        }
        if (!reuseAct) {
            const float* am = (phase == 0) ? g_agg : (phase == 1) ? h : x;
            for (int i = tid; i < DN * 64; i += 256) {
                int k = i & 63, n = i >> 6;           // k fast -> gmem coalesced
                int gn = base + n;
                s_act[k * AP + n] = (gn < N) ? am[gn * FEAT + k] : 0.f;
            }
        }
        __syncthreads();

#pragma unroll 4
        for (int k = 0; k < 64; k++) {
            float4 w4 = *(const float4*)&s_w[k * WP + d0];
            ull wd[4];
            wd[0] = dup2(w4.x); wd[1] = dup2(w4.y);
            wd[2] = dup2(w4.z); wd[3] = dup2(w4.w);
            longlong2 p01 = *(const longlong2*)&s_act[k * AP + n0];
            longlong2 p23 = *(const longlong2*)&s_act[k * AP + n0 + 4];
            ull av[4];
            av[0] = (ull)p01.x; av[1] = (ull)p01.y;
            av[2] = (ull)p23.x; av[3] = (ull)p23.y;
#pragma unroll
            for (int dd = 0; dd < 4; dd++)
#pragma unroll
                for (int p = 0; p < 4; p++)
                    fma2(acc[dd][p], av[p], wd[dd]);
        }

        if (phase == 1) {
            // mid-epilogue in registers: acc = PReLU(acc + bl)
#pragma unroll
            for (int dd = 0; dd < 4; dd++)
#pragma unroll
                for (int p = 0; p < 4; p++) {
                    float lo, hi;
                    unpk(lo, hi, acc[dd][p]);
                    lo += bl[dd]; hi += bl[dd];
                    lo = (lo >= 0.f) ? lo : apar[dd] * lo;
                    hi = (hi >= 0.f) ? hi : apar[dd] * hi;
                    acc[dd][p] = pk2(lo, hi);
                }
        }
    }

    // final epilogue: out = acc + bs
    float* dstp = outToH1 ? g_h1 : out;
    float f[4][8];
#pragma unroll
    for (int dd = 0; dd < 4; dd++)
#pragma unroll
        for (int p = 0; p < 4; p++)
            unpk(f[dd][2 * p], f[dd][2 * p + 1], acc[dd][p]);
#pragma unroll
    for (int j = 0; j < 8; j++) {
        int gn = base + n0 + j;
        if (gn < N) {
            float4 v;
            v.x = f[0][j] + bs[0];
            v.y = f[1][j] + bs[1];
            v.z = f[2][j] + bs[2];
            v.w = f[3][j] + bs[3];
            *(float4*)&dstp[gn * FEAT + d0] = v;
        }
    }
}

// ---------------------------------------------------------------------------
// Cleanup: restore call-entry invariants (g_cnt=0, g_bar=0).
// ---------------------------------------------------------------------------
__global__ void cleanup_kernel(int N)
{
    int i = blockIdx.x * blockDim.x + threadIdx.x;
    if (i < N) g_cnt[i] = 0;
    if (i == 0) g_bar = 0;
}

// ---------------------------------------------------------------------------
// Launch sequence. Index 3 (ncu profiled slot) = layer-0 dense_kernel.
// ---------------------------------------------------------------------------
extern "C" void kernel_launch(void* const* d_in, const int* in_sizes, int n_in,
                              void* d_out, int out_size)
{
    const float* x  = (const float*)d_in[0];
    const int*   ei = (const int*)d_in[1];   // int32 (JAX x64 disabled)
    int N = in_sizes[0] / FEAT;
    int E = in_sizes[1] / 2;
    const int* src = ei;
    const int* dst = ei + E;

    const float* w_l0    = (const float*)d_in[2];
    const float* b_l0    = (const float*)d_in[3];
    const float* w_r0    = (const float*)d_in[4];
    const float* w_skip0 = (const float*)d_in[5];
    const float* b_skip0 = (const float*)d_in[6];
    const float* a0      = (const float*)d_in[7];
    const float* w_l1    = (const float*)d_in[8];
    const float* b_l1    = (const float*)d_in[9];
    const float* w_r1    = (const float*)d_in[10];
    const float* w_skip1 = (const float*)d_in[11];
    const float* b_skip1 = (const float*)d_in[12];
    const float* a1      = (const float*)d_in[13];
    float* out = (float*)d_out;

    size_t dsmem = (size_t)(64 * WP + 64 * AP) * sizeof(float); // 51,200 B
    cudaFuncSetAttribute(dense_kernel, cudaFuncAttributeMaxDynamicSharedMemorySize,
                         (int)dsmem);

    int eblocks = (E + 255) / 256;
    int nb      = (N + SCAN_CHUNK - 1) / SCAN_CHUNK;   // 49
    int ablocks = (N * 32 + 255) / 256;
    int dblocks = (N + DN - 1) / DN;
    int nblocks = (N + 255) / 256;

    hist_kernel<<<eblocks, 256>>>(dst, E);                           // 0
    scanfill_kernel<<<nb, 256>>>(src, dst, N, E, nb);                // 1

    agg_kernel<<<ablocks, 256>>>(x, N, 0);                           // 2
    dense_kernel<<<dblocks, 256, dsmem>>>(x, w_l0, b_l0, w_r0,       // 3 <- profiled
                                          w_skip0, b_skip0, a0,
                                          out, N, 0, 1);

    agg_kernel<<<ablocks, 256>>>(x, N, 1);                           // 4
    dense_kernel<<<dblocks, 256, dsmem>>>(x, w_l1, b_l1, w_r1,       // 5
                                          w_skip1, b_skip1, a1,
                                          out, N, 1, 0);

    cleanup_kernel<<<nblocks, 256>>>(N);                             // 6
}